// round 14
// baseline (speedup 1.0000x reference)
#include <cuda_runtime.h>
#include <cuda_fp16.h>
#include <cstdint>
#include <cstddef>

#define EMBED    256
#define HEADS    8
#define LEVELS   4
#define POINTS   4
#define HEAD_DIM 32

// ---------------------------------------------------------------------------
// Scratch (static __device__ globals; runtime allocation is forbidden)
// ---------------------------------------------------------------------------
__device__ __half g_af16[53248 * 256];          // value (fp16 input to vproj)
__device__ __half g_vph [53248 * 256];          // projected value (fp16)
__device__ __half g_wf16[512 * 256];            // w_value rows 0-255, w_out 256-511
__device__ float  g_off  [3600 * EMBED];        // sampling offsets
__device__ float  g_logit[3600 * 128];          // attn logits
__device__ __half g_sampf16[3712 * 512];        // sampled out: fp16 hi|lo chunked

// ---------------------------------------------------------------------------
// helpers
// ---------------------------------------------------------------------------
__device__ __forceinline__ uint32_t smem_u32(const void* p) {
    uint32_t a;
    asm("{ .reg .u64 t; cvta.to.shared.u64 t, %1; cvt.u32.u64 %0, t; }"
        : "=r"(a) : "l"(p));
    return a;
}

__device__ __forceinline__ void ldsm4(uint32_t* r, uint32_t addr) {
    asm volatile("ldmatrix.sync.aligned.m8n8.x4.shared.b16 {%0,%1,%2,%3}, [%4];"
                 : "=r"(r[0]), "=r"(r[1]), "=r"(r[2]), "=r"(r[3]) : "r"(addr));
}

__device__ __forceinline__ void mma_f16(float* c, const uint32_t* a,
                                        uint32_t b0, uint32_t b1) {
    asm volatile(
        "mma.sync.aligned.m16n8k16.row.col.f32.f16.f16.f32 "
        "{%0,%1,%2,%3}, {%4,%5,%6,%7}, {%8,%9}, {%0,%1,%2,%3};"
        : "+f"(c[0]), "+f"(c[1]), "+f"(c[2]), "+f"(c[3])
        : "r"(a[0]), "r"(a[1]), "r"(a[2]), "r"(a[3]), "r"(b0), "r"(b1));
}

__device__ __forceinline__ void cp_async16(uint32_t saddr, const void* gaddr) {
    asm volatile("cp.async.cg.shared.global [%0], [%1], 16;"
                 :: "r"(saddr), "l"(gaddr) : "memory");
}
#define CP_ASYNC_COMMIT() asm volatile("cp.async.commit_group;" ::: "memory")
#define CP_ASYNC_WAIT(N)  asm volatile("cp.async.wait_group %0;" :: "n"(N) : "memory")

union Pack8h { uint4 u; __half b[8]; __half2 h2[4]; };

#define SWZ(o) ((o) ^ (((o) >> 3) & 0x70))

// ---------------------------------------------------------------------------
// Convert: value -> plain fp16 (rows of 256); weights (w_value then w_out)
// -> plain fp16 rows of 256.
// ---------------------------------------------------------------------------
__global__ __launch_bounds__(256)
void cvt_f16(const float* __restrict__ A, const float* __restrict__ Wv,
             const float* __restrict__ Wo,
             __half* __restrict__ Af, __half* __restrict__ Wf, int Mv)
{
    int t = blockIdx.x * 256 + threadIdx.x;      // one thread per 8 floats
    int total = (Mv + 512) * 32;
    if (t >= total) return;
    int row = t >> 5;
    int s8  = t & 31;
    const float* src;
    __half* dst;
    if (row < Mv) {
        src = A + (size_t)row * 256 + s8 * 8;
        dst = Af + (size_t)row * 256 + s8 * 8;
    } else {
        int r2 = row - Mv;                        // 0..511
        src = (r2 < 256) ? Wv + (size_t)r2 * 256 + s8 * 8
                         : Wo + (size_t)(r2 - 256) * 256 + s8 * 8;
        dst = Wf + (size_t)r2 * 256 + s8 * 8;
    }
    float4 v0 = *(const float4*)(src);
    float4 v1 = *(const float4*)(src + 4);
    Pack8h H;
    H.h2[0] = __floats2half2_rn(v0.x, v0.y);
    H.h2[1] = __floats2half2_rn(v0.z, v0.w);
    H.h2[2] = __floats2half2_rn(v1.x, v1.y);
    H.h2[3] = __floats2half2_rn(v1.z, v1.w);
    *(uint4*)dst = H.u;
}

// ---------------------------------------------------------------------------
// Plain fp16 MMA GEMM body: C[M,256] (fp16) tile 128x128 at (m0,n0).
// ---------------------------------------------------------------------------
__device__ __forceinline__ void mma_gemm_plain(
    const __half* __restrict__ Af, const __half* __restrict__ Wf,
    const float* __restrict__ bias, __half* __restrict__ C,
    int M, int m0, int n0, char* sm)
{
    const int tid  = threadIdx.x;
    const int lane = tid & 31;
    const int w    = tid >> 5;
    const int wm   = (w & 1) * 64;
    const int wn   = (w >> 1) * 32;
    const uint32_t sb = smem_u32(sm);

    float acc[4][4][4] = {};

    auto prefetch = [&](int p, int buf) {
        const uint32_t base = sb + buf * 32768;
        #pragma unroll
        for (int i = 0; i < 8; i++) {
            int idx = tid + i * 256;             // 0..2047
            int r   = (idx >> 3) & 127;
            int seg = idx & 7;
            uint32_t so = SWZ((uint32_t)(r * 128 + seg * 16));
            if (idx < 1024) {
                cp_async16(base + so,
                           Af + ((size_t)(m0 + r) * 256 + p * 64 + seg * 8));
            } else {
                cp_async16(base + 16384 + so,
                           Wf + ((size_t)(n0 + r) * 256 + p * 64 + seg * 8));
            }
        }
    };

    auto compute = [&](int buf) {
        const uint32_t abase = sb + buf * 32768;
        const uint32_t bbase = abase + 16384;
        const int j = lane >> 3, r = lane & 7;
        #pragma unroll
        for (int g = 0; g < 4; g++) {
            uint32_t bfr[2][4];
            #pragma unroll
            for (int nt = 0; nt < 2; nt++) {
                uint32_t row  = wn + nt * 16 + (j >> 1) * 8 + r;
                uint32_t colb = (g * 16 + (j & 1) * 8) * 2;
                ldsm4(bfr[nt], bbase + SWZ(row * 128 + colb));
            }
            #pragma unroll
            for (int mt = 0; mt < 4; mt++) {
                uint32_t af[4];
                uint32_t row  = wm + mt * 16 + (j & 1) * 8 + r;
                uint32_t colb = (g * 16 + (j >> 1) * 8) * 2;
                ldsm4(af, abase + SWZ(row * 128 + colb));
                #pragma unroll
                for (int ns = 0; ns < 4; ns++)
                    mma_f16(acc[mt][ns], af,
                            bfr[ns >> 1][(ns & 1) * 2],
                            bfr[ns >> 1][(ns & 1) * 2 + 1]);
            }
        }
    };

    prefetch(0, 0);
    CP_ASYNC_COMMIT();
    #pragma unroll 1
    for (int p = 0; p < 4; p++) {
        int buf = p & 1;
        if (p + 1 < 4) {
            prefetch(p + 1, buf ^ 1);
            CP_ASYNC_COMMIT();
            CP_ASYNC_WAIT(1);
        } else {
            CP_ASYNC_WAIT(0);
        }
        __syncthreads();
        compute(buf);
        __syncthreads();
    }

    const int g = lane >> 2, tig = lane & 3;
    #pragma unroll
    for (int mt = 0; mt < 4; mt++) {
        int mr = m0 + wm + mt * 16 + g;
        #pragma unroll
        for (int ns = 0; ns < 4; ns++) {
            int col = n0 + wn + ns * 8 + tig * 2;
            float bxv = bias[col], byv = bias[col + 1];
            if (mr < M) {
                __half2 o = __floats2half2_rn(acc[mt][ns][0] + bxv,
                                              acc[mt][ns][1] + byv);
                *(__half2*)&C[(size_t)mr * 256 + col] = o;
            }
            if (mr + 8 < M) {
                __half2 o = __floats2half2_rn(acc[mt][ns][2] + bxv,
                                              acc[mt][ns][3] + byv);
                *(__half2*)&C[(size_t)(mr + 8) * 256 + col] = o;
            }
        }
    }
}

// ---------------------------------------------------------------------------
// SIMT small-GEMM body (64x64 tile) on caller smem: C = A[M,256]*B[N,256]^T+bias
// ---------------------------------------------------------------------------
__device__ void gemm_small_body(const float* __restrict__ A,
                                const float* __restrict__ B,
                                const float* __restrict__ bias,
                                float* __restrict__ C,
                                int M, int N, int m0, int n0, char* smraw)
{
    float (*As)[68] = (float (*)[68])smraw;
    float (*Bs)[68] = (float (*)[68])(smraw + 32 * 68 * 4);

    const int tid = threadIdx.x;
    const int tx  = tid & 15;
    const int ty  = tid >> 4;

    float acc[4][4] = {};

    for (int k0 = 0; k0 < 256; k0 += 32) {
        #pragma unroll
        for (int i = 0; i < 2; i++) {
            int idx = tid + i * 256;
            int r   = idx >> 3;
            int c4  = idx & 7;
            int m   = m0 + r;
            float4 av = (m < M) ? *(const float4*)&A[(size_t)m * 256 + k0 + c4 * 4]
                                : make_float4(0.f, 0.f, 0.f, 0.f);
            As[c4 * 4 + 0][r] = av.x;
            As[c4 * 4 + 1][r] = av.y;
            As[c4 * 4 + 2][r] = av.z;
            As[c4 * 4 + 3][r] = av.w;
            int n   = n0 + r;
            float4 bv = (n < N) ? *(const float4*)&B[(size_t)n * 256 + k0 + c4 * 4]
                                : make_float4(0.f, 0.f, 0.f, 0.f);
            Bs[c4 * 4 + 0][r] = bv.x;
            Bs[c4 * 4 + 1][r] = bv.y;
            Bs[c4 * 4 + 2][r] = bv.z;
            Bs[c4 * 4 + 3][r] = bv.w;
        }
        __syncthreads();

        #pragma unroll
        for (int kk = 0; kk < 32; kk++) {
            float4 a = *(const float4*)&As[kk][ty * 4];
            float4 b = *(const float4*)&Bs[kk][tx * 4];
            acc[0][0] += a.x * b.x; acc[0][1] += a.x * b.y;
            acc[0][2] += a.x * b.z; acc[0][3] += a.x * b.w;
            acc[1][0] += a.y * b.x; acc[1][1] += a.y * b.y;
            acc[1][2] += a.y * b.z; acc[1][3] += a.y * b.w;
            acc[2][0] += a.z * b.x; acc[2][1] += a.z * b.y;
            acc[2][2] += a.z * b.z; acc[2][3] += a.z * b.w;
            acc[3][0] += a.w * b.x; acc[3][1] += a.w * b.y;
            acc[3][2] += a.w * b.z; acc[3][3] += a.w * b.w;
        }
        __syncthreads();
    }

    #pragma unroll
    for (int i = 0; i < 4; i++) {
        int m = m0 + ty * 4 + i;
        if (m >= M) continue;
        #pragma unroll
        for (int j = 0; j < 4; j++) {
            int n = n0 + tx * 4 + j;
            if (n < N) C[(size_t)m * N + n] = acc[i][j] + bias[n];
        }
    }
}

// ---------------------------------------------------------------------------
// Fat kernel (2 CTAs/SM). Small SIMT GEMMs dispatch FIRST.
// ---------------------------------------------------------------------------
__global__ __launch_bounds__(256, 2)
void fat_gemms(const __half* __restrict__ Af, const __half* __restrict__ Wf,
               const float* __restrict__ b_value,
               __half* __restrict__ Cv, int Mv, int MB,
               const float* __restrict__ query,
               const float* __restrict__ w_off, const float* __restrict__ b_off,
               float* __restrict__ offb,
               const float* __restrict__ w_attn, const float* __restrict__ b_attn,
               float* __restrict__ logitb, int Mq)
{
    extern __shared__ char sm[];
    const int bx = blockIdx.x;

    if (bx < 228) {
        gemm_small_body(query, w_off, b_off, offb, Mq, 256,
                        (bx >> 2) * 64, (bx & 3) * 64, sm);
        return;
    }
    if (bx < 342) {
        int ix = bx - 228;
        gemm_small_body(query, w_attn, b_attn, logitb, Mq, 128,
                        (ix >> 1) * 64, (ix & 1) * 64, sm);
        return;
    }
    int vb = bx - 342;
    mma_gemm_plain(Af, Wf, b_value, Cv, Mv, (vb >> 1) * 128, (vb & 1) * 128, sm);
}

// ---------------------------------------------------------------------------
// Output projection, tile 32x256, 2-term split A (samp hi|lo chunked),
// plain fp16 W (w_out at row offset 256). One CTA per 32 query rows.
// ---------------------------------------------------------------------------
__global__ __launch_bounds__(256)
void outproj_mma32(const __half* __restrict__ Sf, const __half* __restrict__ Wf,
                   const float* __restrict__ b_out, float* __restrict__ C, int Mq)
{
    extern __shared__ char sm[];
    const int tid  = threadIdx.x;
    const int lane = tid & 31;
    const int w    = tid >> 5;
    const int wn   = w * 32;                 // each warp owns 32 output cols
    const int m0   = blockIdx.x * 32;
    const uint32_t sb = smem_u32(sm);
    const __half* Wo = Wf + 256 * 256;

    float acc[2][4][4] = {};

    auto prefetch = [&](int p, int buf) {
        const uint32_t base = sb + buf * 40960;
        #pragma unroll
        for (int i = 0; i < 10; i++) {
            int idx = tid + i * 256;         // 0..2559
            if (idx < 512) {                 // A: 2 subtiles of 32 rows x 128B
                int tc  = idx >> 8;
                int r   = (idx >> 3) & 31;
                int seg = idx & 7;
                cp_async16(base + tc * 4096 + SWZ((uint32_t)(r * 128 + seg * 16)),
                           Sf + ((size_t)(m0 + r) * 512 + (p * 2 + tc) * 64 + seg * 8));
            } else {                         // B: 256 rows x 128B
                int i2  = idx - 512;
                int r   = i2 >> 3;
                int seg = i2 & 7;
                cp_async16(base + 8192 + SWZ((uint32_t)(r * 128 + seg * 16)),
                           Wo + ((size_t)r * 256 + p * 64 + seg * 8));
            }
        }
    };

    auto compute = [&](int buf) {
        const uint32_t base  = sb + buf * 40960;
        const uint32_t bbase = base + 8192;
        const int j = lane >> 3, r = lane & 7;
        #pragma unroll
        for (int c = 0; c < 2; c++) {
            #pragma unroll
            for (int g = 0; g < 2; g++) {
                uint32_t bfr[2][4];
                #pragma unroll
                for (int nt = 0; nt < 2; nt++) {
                    uint32_t row  = wn + nt * 16 + (j >> 1) * 8 + r;
                    uint32_t colb = (c * 32 + g * 16 + (j & 1) * 8) * 2;
                    ldsm4(bfr[nt], bbase + SWZ(row * 128 + colb));
                }
                #pragma unroll
                for (int t = 0; t < 2; t++) {
                    #pragma unroll
                    for (int mt = 0; mt < 2; mt++) {
                        uint32_t af[4];
                        uint32_t row  = mt * 16 + (j & 1) * 8 + r;
                        uint32_t colb = (t * 32 + g * 16 + (j >> 1) * 8) * 2;
                        ldsm4(af, base + c * 4096 + SWZ(row * 128 + colb));
                        #pragma unroll
                        for (int ns = 0; ns < 4; ns++)
                            mma_f16(acc[mt][ns], af,
                                    bfr[ns >> 1][(ns & 1) * 2],
                                    bfr[ns >> 1][(ns & 1) * 2 + 1]);
                    }
                }
            }
        }
    };

    prefetch(0, 0);
    CP_ASYNC_COMMIT();
    #pragma unroll 1
    for (int p = 0; p < 4; p++) {
        int buf = p & 1;
        if (p + 1 < 4) {
            prefetch(p + 1, buf ^ 1);
            CP_ASYNC_COMMIT();
            CP_ASYNC_WAIT(1);
        } else {
            CP_ASYNC_WAIT(0);
        }
        __syncthreads();
        compute(buf);
        __syncthreads();
    }

    const int g = lane >> 2, tig = lane & 3;
    #pragma unroll
    for (int mt = 0; mt < 2; mt++) {
        int mr = m0 + mt * 16 + g;
        #pragma unroll
        for (int ns = 0; ns < 4; ns++) {
            int col = wn + ns * 8 + tig * 2;
            float bxv = b_out[col], byv = b_out[col + 1];
            if (mr < Mq) {
                float2 o = {acc[mt][ns][0] + bxv, acc[mt][ns][1] + byv};
                *(float2*)&C[(size_t)mr * 256 + col] = o;
            }
            if (mr + 8 < Mq) {
                float2 o = {acc[mt][ns][2] + bxv, acc[mt][ns][3] + byv};
                *(float2*)&C[(size_t)(mr + 8) * 256 + col] = o;
            }
        }
    }
}

// ---------------------------------------------------------------------------
// Deformable sampling v3: TWO queries per block, half2 gathers.
// Phase 1: 256 threads = 2 queries x 128 (h,l,p) combos -> idx/weights.
// Phase 2: thread = (q, h, d2); each thread covers 2 dims via __half2 loads.
// ---------------------------------------------------------------------------
__global__ __launch_bounds__(256)
void msda_sample2(const __half* __restrict__ vproj,
                  const float* __restrict__ refp,
                  const float* __restrict__ off,
                  const float* __restrict__ logits,
                  const int*   __restrict__ shapes,
                  const int*   __restrict__ lstart,
                  __half* __restrict__ sampf,     // [3712, 512] chunked hi|lo
                  int Lq, int Lv)
{
    const int bq0 = blockIdx.x * 2;
    const int tid = threadIdx.x;
    const int q   = tid >> 7;            // 0/1: query within pair
    const int c   = tid & 127;           // combo / lane-within-query

    __shared__ float s_log[2][128];
    __shared__ float s_off[2][256];
    __shared__ float s_ref[2][8];
    __shared__ int   s_shape[8];
    __shared__ int   s_start[4];
    __shared__ int4   s_idx4[2][128];
    __shared__ float4 s_w4[2][128];

    s_log[q][c]       = logits[(size_t)(bq0 + q) * 128 + c];
    s_off[q][c]       = off[(size_t)(bq0 + q) * 256 + c];
    s_off[q][c + 128] = off[(size_t)(bq0 + q) * 256 + c + 128];
    if (tid < 16) s_ref[tid >> 3][tid & 7] =
        refp[(size_t)(bq0 + (tid >> 3)) * 8 + (tid & 7)];
    if (tid < 8) s_shape[tid] = shapes[tid];
    if (tid < 4) s_start[tid] = lstart[tid];
    __syncthreads();

    // ---- phase 1: one combo per thread ----
    {
        const int h = c >> 4;
        const int l = (c >> 2) & 3;

        float mx = -1e30f;
        #pragma unroll
        for (int j = 0; j < 16; j++) mx = fmaxf(mx, s_log[q][h * 16 + j]);
        float sum = 0.f;
        #pragma unroll
        for (int j = 0; j < 16; j++) sum += __expf(s_log[q][h * 16 + j] - mx);
        const float aw = __expf(s_log[q][c] - mx) / sum;

        const int   Hh = s_shape[l * 2 + 0];
        const int   Ww = s_shape[l * 2 + 1];
        const float Wfl = (float)Ww, Hfl = (float)Hh;
        const int   st = s_start[l];
        const float rx = s_ref[q][l * 2 + 0];
        const float ry = s_ref[q][l * 2 + 1];

        const float x = (rx + s_off[q][c * 2 + 0] / Wfl) * Wfl - 0.5f;
        const float y = (ry + s_off[q][c * 2 + 1] / Hfl) * Hfl - 0.5f;
        const float x0f = floorf(x), y0f = floorf(y);
        const float lx = x - x0f, ly = y - y0f;
        const int   x0 = (int)x0f, y0 = (int)y0f;

        const bool vx0 = (x0 >= 0) & (x0 < Ww);
        const bool vx1 = (x0 + 1 >= 0) & (x0 + 1 < Ww);
        const bool vy0 = (y0 >= 0) & (y0 < Hh);
        const bool vy1 = (y0 + 1 >= 0) & (y0 + 1 < Hh);

        int4 id;
        id.x = (vy0 && vx0) ? st + y0 * Ww + x0           : -1;
        id.y = (vy0 && vx1) ? st + y0 * Ww + x0 + 1       : -1;
        id.z = (vy1 && vx0) ? st + (y0 + 1) * Ww + x0     : -1;
        id.w = (vy1 && vx1) ? st + (y0 + 1) * Ww + x0 + 1 : -1;

        float4 ww;
        ww.x = aw * (1.f - lx) * (1.f - ly);
        ww.y = aw * lx * (1.f - ly);
        ww.z = aw * (1.f - lx) * ly;
        ww.w = aw * lx * ly;

        s_idx4[q][c] = id;
        s_w4[q][c]   = ww;
    }
    __syncthreads();

    // ---- phase 2: thread (q, h, d2); 2 dims via half2 ----
    const int h  = c >> 4;
    const int d2 = c & 15;
    const int bq = bq0 + q;
    const int b  = bq / Lq;
    const __half2* vb = (const __half2*)(vproj + (size_t)b * Lv * EMBED
                                         + h * HEAD_DIM + d2 * 2);

    float2 a0 = {0.f, 0.f}, a1 = {0.f, 0.f}, a2 = {0.f, 0.f}, a3 = {0.f, 0.f};
    #pragma unroll 4
    for (int i = 0; i < 16; i++) {
        const int t = h * 16 + i;
        const int4   id = s_idx4[q][t];
        const float4 ww = s_w4[q][t];
        if (id.x >= 0) {
            float2 f = __half22float2(__ldg(vb + (size_t)id.x * 128));
            a0.x += ww.x * f.x; a0.y += ww.x * f.y;
        }
        if (id.y >= 0) {
            float2 f = __half22float2(__ldg(vb + (size_t)id.y * 128));
            a1.x += ww.y * f.x; a1.y += ww.y * f.y;
        }
        if (id.z >= 0) {
            float2 f = __half22float2(__ldg(vb + (size_t)id.z * 128));
            a2.x += ww.z * f.x; a2.y += ww.z * f.y;
        }
        if (id.w >= 0) {
            float2 f = __half22float2(__ldg(vb + (size_t)id.w * 128));
            a3.x += ww.w * f.x; a3.y += ww.w * f.y;
        }
    }
    const float rx2 = (a0.x + a1.x) + (a2.x + a3.x);
    const float ry2 = (a0.y + a1.y) + (a2.y + a3.y);

    // write hi|lo split, two contiguous dims -> half2 stores
    __half hx = __float2half_rn(rx2);
    __half hy = __float2half_rn(ry2);
    __half lx2 = __float2half_rn(rx2 - __half2float(hx));
    __half ly2 = __float2half_rn(ry2 - __half2float(hy));
    __half2* dst = (__half2*)(sampf + (size_t)bq * 512 + h * 64 + d2 * 2);
    dst[0]  = __halves2half2(hx, hy);
    dst[16] = __halves2half2(lx2, ly2);   // +32 halves
}

// ---------------------------------------------------------------------------
// kernel_launch
// ---------------------------------------------------------------------------
extern "C" void kernel_launch(void* const* d_in, const int* in_sizes, int n_in,
                              void* d_out, int out_size)
{
    const float* query   = (const float*)d_in[0];
    const float* refp    = (const float*)d_in[1];
    const float* value   = (const float*)d_in[2];
    const int*   shapes  = (const int*)  d_in[3];
    const int*   lstart  = (const int*)  d_in[4];
    const float* w_value = (const float*)d_in[5];
    const float* b_value = (const float*)d_in[6];
    const float* w_off   = (const float*)d_in[7];
    const float* b_off   = (const float*)d_in[8];
    const float* w_attn  = (const float*)d_in[9];
    const float* b_attn  = (const float*)d_in[10];
    const float* w_out   = (const float*)d_in[11];
    const float* b_out   = (const float*)d_in[12];

    const int Mv = in_sizes[2] / EMBED;   // bs * Lv = 53176
    const int Mq = in_sizes[0] / EMBED;   // bs * Lq = 3600
    const int bs = 4;
    const int Lv = Mv / bs;
    const int Lq = Mq / bs;

    float *offb, *logitb;
    __half *af, *vph, *wf, *sf;
    cudaGetSymbolAddress((void**)&offb,   g_off);
    cudaGetSymbolAddress((void**)&logitb, g_logit);
    cudaGetSymbolAddress((void**)&af,     g_af16);
    cudaGetSymbolAddress((void**)&vph,    g_vph);
    cudaGetSymbolAddress((void**)&wf,     g_wf16);
    cudaGetSymbolAddress((void**)&sf,     g_sampf16);

    // 1) convert value + weights to fp16
    {
        int total = (Mv + 512) * 32;
        cvt_f16<<<(total + 255) / 256, 256>>>(value, w_value, w_out, af, wf, Mv);
    }

    // 2) fat kernel: small GEMMs first, then vproj (fp16 tensor) -> fp16 out
    const int MB = (Mv + 127) / 128;               // 416
    static bool cfg = false;
    if (!cfg) {
        cudaFuncSetAttribute(fat_gemms,
                             cudaFuncAttributeMaxDynamicSharedMemorySize, 65536);
        cudaFuncSetAttribute(outproj_mma32,
                             cudaFuncAttributeMaxDynamicSharedMemorySize, 81920);
        cfg = true;
    }
    fat_gemms<<<342 + 2 * MB, 256, 65536>>>(
        af, wf, b_value, vph, Mv, MB,
        query, w_off, b_off, offb, w_attn, b_attn, logitb, Mq);

    // 3) sampling: 2 queries per block, half2 gathers -> fp16 split
    msda_sample2<<<Mq / 2, 256>>>(vph, refp, offb, logitb, shapes, lstart,
                                  sf, Lq, Lv);

    // 4) output projection (fp16, 2-term samp split, 32-row tiles) -> d_out
    outproj_mma32<<<(Mq + 31) / 32, 256, 81920>>>(sf, wf, b_out, (float*)d_out, Mq);
}

// round 15
// speedup vs baseline: 1.4670x; 1.4670x over previous
#include <cuda_runtime.h>
#include <cuda_fp16.h>
#include <cstdint>
#include <cstddef>

#define EMBED    256
#define HEADS    8
#define LEVELS   4
#define POINTS   4
#define HEAD_DIM 32

// ---------------------------------------------------------------------------
// Scratch (static __device__ globals; runtime allocation is forbidden)
// ---------------------------------------------------------------------------
__device__ __half g_af16[53248 * 256];          // value (fp16 input to vproj)
__device__ __half g_vph [53248 * 256];          // projected value (fp16)
__device__ __half g_wf16[512 * 256];            // w_value rows 0-255, w_out 256-511
__device__ float  g_off  [3600 * EMBED];        // sampling offsets
__device__ float  g_logit[3600 * 128];          // attn logits
__device__ __half g_sampf16[3712 * 512];        // sampled out: fp16 hi|lo chunked

// ---------------------------------------------------------------------------
// helpers
// ---------------------------------------------------------------------------
__device__ __forceinline__ uint32_t smem_u32(const void* p) {
    uint32_t a;
    asm("{ .reg .u64 t; cvta.to.shared.u64 t, %1; cvt.u32.u64 %0, t; }"
        : "=r"(a) : "l"(p));
    return a;
}

__device__ __forceinline__ void ldsm4(uint32_t* r, uint32_t addr) {
    asm volatile("ldmatrix.sync.aligned.m8n8.x4.shared.b16 {%0,%1,%2,%3}, [%4];"
                 : "=r"(r[0]), "=r"(r[1]), "=r"(r[2]), "=r"(r[3]) : "r"(addr));
}

__device__ __forceinline__ void mma_f16(float* c, const uint32_t* a,
                                        uint32_t b0, uint32_t b1) {
    asm volatile(
        "mma.sync.aligned.m16n8k16.row.col.f32.f16.f16.f32 "
        "{%0,%1,%2,%3}, {%4,%5,%6,%7}, {%8,%9}, {%0,%1,%2,%3};"
        : "+f"(c[0]), "+f"(c[1]), "+f"(c[2]), "+f"(c[3])
        : "r"(a[0]), "r"(a[1]), "r"(a[2]), "r"(a[3]), "r"(b0), "r"(b1));
}

__device__ __forceinline__ void cp_async16(uint32_t saddr, const void* gaddr) {
    asm volatile("cp.async.cg.shared.global [%0], [%1], 16;"
                 :: "r"(saddr), "l"(gaddr) : "memory");
}
#define CP_ASYNC_COMMIT() asm volatile("cp.async.commit_group;" ::: "memory")
#define CP_ASYNC_WAIT(N)  asm volatile("cp.async.wait_group %0;" :: "n"(N) : "memory")

union Pack8h { uint4 u; __half b[8]; __half2 h2[4]; };

#define SWZ(o) ((o) ^ (((o) >> 3) & 0x70))

// ---------------------------------------------------------------------------
// Convert: value -> plain fp16 (rows of 256); weights (w_value then w_out)
// -> plain fp16 rows of 256.
// ---------------------------------------------------------------------------
__global__ __launch_bounds__(256)
void cvt_f16(const float* __restrict__ A, const float* __restrict__ Wv,
             const float* __restrict__ Wo,
             __half* __restrict__ Af, __half* __restrict__ Wf, int Mv)
{
    int t = blockIdx.x * 256 + threadIdx.x;      // one thread per 8 floats
    int total = (Mv + 512) * 32;
    if (t >= total) return;
    int row = t >> 5;
    int s8  = t & 31;
    const float* src;
    __half* dst;
    if (row < Mv) {
        src = A + (size_t)row * 256 + s8 * 8;
        dst = Af + (size_t)row * 256 + s8 * 8;
    } else {
        int r2 = row - Mv;                        // 0..511
        src = (r2 < 256) ? Wv + (size_t)r2 * 256 + s8 * 8
                         : Wo + (size_t)(r2 - 256) * 256 + s8 * 8;
        dst = Wf + (size_t)r2 * 256 + s8 * 8;
    }
    float4 v0 = *(const float4*)(src);
    float4 v1 = *(const float4*)(src + 4);
    Pack8h H;
    H.h2[0] = __floats2half2_rn(v0.x, v0.y);
    H.h2[1] = __floats2half2_rn(v0.z, v0.w);
    H.h2[2] = __floats2half2_rn(v1.x, v1.y);
    H.h2[3] = __floats2half2_rn(v1.z, v1.w);
    *(uint4*)dst = H.u;
}

// ---------------------------------------------------------------------------
// Plain fp16 MMA GEMM body: C[M,256] (fp16) tile 128x128 at (m0,n0).
// ---------------------------------------------------------------------------
__device__ __forceinline__ void mma_gemm_plain(
    const __half* __restrict__ Af, const __half* __restrict__ Wf,
    const float* __restrict__ bias, __half* __restrict__ C,
    int M, int m0, int n0, char* sm)
{
    const int tid  = threadIdx.x;
    const int lane = tid & 31;
    const int w    = tid >> 5;
    const int wm   = (w & 1) * 64;
    const int wn   = (w >> 1) * 32;
    const uint32_t sb = smem_u32(sm);

    float acc[4][4][4] = {};

    auto prefetch = [&](int p, int buf) {
        const uint32_t base = sb + buf * 32768;
        #pragma unroll
        for (int i = 0; i < 8; i++) {
            int idx = tid + i * 256;             // 0..2047
            int r   = (idx >> 3) & 127;
            int seg = idx & 7;
            uint32_t so = SWZ((uint32_t)(r * 128 + seg * 16));
            if (idx < 1024) {
                cp_async16(base + so,
                           Af + ((size_t)(m0 + r) * 256 + p * 64 + seg * 8));
            } else {
                cp_async16(base + 16384 + so,
                           Wf + ((size_t)(n0 + r) * 256 + p * 64 + seg * 8));
            }
        }
    };

    auto compute = [&](int buf) {
        const uint32_t abase = sb + buf * 32768;
        const uint32_t bbase = abase + 16384;
        const int j = lane >> 3, r = lane & 7;
        #pragma unroll
        for (int g = 0; g < 4; g++) {
            uint32_t bfr[2][4];
            #pragma unroll
            for (int nt = 0; nt < 2; nt++) {
                uint32_t row  = wn + nt * 16 + (j >> 1) * 8 + r;
                uint32_t colb = (g * 16 + (j & 1) * 8) * 2;
                ldsm4(bfr[nt], bbase + SWZ(row * 128 + colb));
            }
            #pragma unroll
            for (int mt = 0; mt < 4; mt++) {
                uint32_t af[4];
                uint32_t row  = wm + mt * 16 + (j & 1) * 8 + r;
                uint32_t colb = (g * 16 + (j >> 1) * 8) * 2;
                ldsm4(af, abase + SWZ(row * 128 + colb));
                #pragma unroll
                for (int ns = 0; ns < 4; ns++)
                    mma_f16(acc[mt][ns], af,
                            bfr[ns >> 1][(ns & 1) * 2],
                            bfr[ns >> 1][(ns & 1) * 2 + 1]);
            }
        }
    };

    prefetch(0, 0);
    CP_ASYNC_COMMIT();
    #pragma unroll 1
    for (int p = 0; p < 4; p++) {
        int buf = p & 1;
        if (p + 1 < 4) {
            prefetch(p + 1, buf ^ 1);
            CP_ASYNC_COMMIT();
            CP_ASYNC_WAIT(1);
        } else {
            CP_ASYNC_WAIT(0);
        }
        __syncthreads();
        compute(buf);
        __syncthreads();
    }

    const int g = lane >> 2, tig = lane & 3;
    #pragma unroll
    for (int mt = 0; mt < 4; mt++) {
        int mr = m0 + wm + mt * 16 + g;
        #pragma unroll
        for (int ns = 0; ns < 4; ns++) {
            int col = n0 + wn + ns * 8 + tig * 2;
            float bxv = bias[col], byv = bias[col + 1];
            if (mr < M) {
                __half2 o = __floats2half2_rn(acc[mt][ns][0] + bxv,
                                              acc[mt][ns][1] + byv);
                *(__half2*)&C[(size_t)mr * 256 + col] = o;
            }
            if (mr + 8 < M) {
                __half2 o = __floats2half2_rn(acc[mt][ns][2] + bxv,
                                              acc[mt][ns][3] + byv);
                *(__half2*)&C[(size_t)(mr + 8) * 256 + col] = o;
            }
        }
    }
}

// ---------------------------------------------------------------------------
// SIMT small-GEMM body (64x64 tile) on caller smem: C = A[M,256]*B[N,256]^T+bias
// ---------------------------------------------------------------------------
__device__ void gemm_small_body(const float* __restrict__ A,
                                const float* __restrict__ B,
                                const float* __restrict__ bias,
                                float* __restrict__ C,
                                int M, int N, int m0, int n0, char* smraw)
{
    float (*As)[68] = (float (*)[68])smraw;
    float (*Bs)[68] = (float (*)[68])(smraw + 32 * 68 * 4);

    const int tid = threadIdx.x;
    const int tx  = tid & 15;
    const int ty  = tid >> 4;

    float acc[4][4] = {};

    for (int k0 = 0; k0 < 256; k0 += 32) {
        #pragma unroll
        for (int i = 0; i < 2; i++) {
            int idx = tid + i * 256;
            int r   = idx >> 3;
            int c4  = idx & 7;
            int m   = m0 + r;
            float4 av = (m < M) ? *(const float4*)&A[(size_t)m * 256 + k0 + c4 * 4]
                                : make_float4(0.f, 0.f, 0.f, 0.f);
            As[c4 * 4 + 0][r] = av.x;
            As[c4 * 4 + 1][r] = av.y;
            As[c4 * 4 + 2][r] = av.z;
            As[c4 * 4 + 3][r] = av.w;
            int n   = n0 + r;
            float4 bv = (n < N) ? *(const float4*)&B[(size_t)n * 256 + k0 + c4 * 4]
                                : make_float4(0.f, 0.f, 0.f, 0.f);
            Bs[c4 * 4 + 0][r] = bv.x;
            Bs[c4 * 4 + 1][r] = bv.y;
            Bs[c4 * 4 + 2][r] = bv.z;
            Bs[c4 * 4 + 3][r] = bv.w;
        }
        __syncthreads();

        #pragma unroll
        for (int kk = 0; kk < 32; kk++) {
            float4 a = *(const float4*)&As[kk][ty * 4];
            float4 b = *(const float4*)&Bs[kk][tx * 4];
            acc[0][0] += a.x * b.x; acc[0][1] += a.x * b.y;
            acc[0][2] += a.x * b.z; acc[0][3] += a.x * b.w;
            acc[1][0] += a.y * b.x; acc[1][1] += a.y * b.y;
            acc[1][2] += a.y * b.z; acc[1][3] += a.y * b.w;
            acc[2][0] += a.z * b.x; acc[2][1] += a.z * b.y;
            acc[2][2] += a.z * b.z; acc[2][3] += a.z * b.w;
            acc[3][0] += a.w * b.x; acc[3][1] += a.w * b.y;
            acc[3][2] += a.w * b.z; acc[3][3] += a.w * b.w;
        }
        __syncthreads();
    }

    #pragma unroll
    for (int i = 0; i < 4; i++) {
        int m = m0 + ty * 4 + i;
        if (m >= M) continue;
        #pragma unroll
        for (int j = 0; j < 4; j++) {
            int n = n0 + tx * 4 + j;
            if (n < N) C[(size_t)m * N + n] = acc[i][j] + bias[n];
        }
    }
}

// ---------------------------------------------------------------------------
// Fat kernel (2 CTAs/SM). Small SIMT GEMMs dispatch FIRST.
// ---------------------------------------------------------------------------
__global__ __launch_bounds__(256, 2)
void fat_gemms(const __half* __restrict__ Af, const __half* __restrict__ Wf,
               const float* __restrict__ b_value,
               __half* __restrict__ Cv, int Mv, int MB,
               const float* __restrict__ query,
               const float* __restrict__ w_off, const float* __restrict__ b_off,
               float* __restrict__ offb,
               const float* __restrict__ w_attn, const float* __restrict__ b_attn,
               float* __restrict__ logitb, int Mq)
{
    extern __shared__ char sm[];
    const int bx = blockIdx.x;

    if (bx < 228) {
        gemm_small_body(query, w_off, b_off, offb, Mq, 256,
                        (bx >> 2) * 64, (bx & 3) * 64, sm);
        return;
    }
    if (bx < 342) {
        int ix = bx - 228;
        gemm_small_body(query, w_attn, b_attn, logitb, Mq, 128,
                        (ix >> 1) * 64, (ix & 1) * 64, sm);
        return;
    }
    int vb = bx - 342;
    mma_gemm_plain(Af, Wf, b_value, Cv, Mv, (vb >> 1) * 128, (vb & 1) * 128, sm);
}

// ---------------------------------------------------------------------------
// Output projection, tile 32x256, 2-term split A (samp hi|lo chunked),
// plain fp16 W (w_out at row offset 256). One CTA per 32 query rows.
// ---------------------------------------------------------------------------
__global__ __launch_bounds__(256)
void outproj_mma32(const __half* __restrict__ Sf, const __half* __restrict__ Wf,
                   const float* __restrict__ b_out, float* __restrict__ C, int Mq)
{
    extern __shared__ char sm[];
    const int tid  = threadIdx.x;
    const int lane = tid & 31;
    const int w    = tid >> 5;
    const int wn   = w * 32;                 // each warp owns 32 output cols
    const int m0   = blockIdx.x * 32;
    const uint32_t sb = smem_u32(sm);
    const __half* Wo = Wf + 256 * 256;

    float acc[2][4][4] = {};

    auto prefetch = [&](int p, int buf) {
        const uint32_t base = sb + buf * 40960;
        #pragma unroll
        for (int i = 0; i < 10; i++) {
            int idx = tid + i * 256;         // 0..2559
            if (idx < 512) {                 // A: 2 subtiles of 32 rows x 128B
                int tc  = idx >> 8;
                int r   = (idx >> 3) & 31;
                int seg = idx & 7;
                cp_async16(base + tc * 4096 + SWZ((uint32_t)(r * 128 + seg * 16)),
                           Sf + ((size_t)(m0 + r) * 512 + (p * 2 + tc) * 64 + seg * 8));
            } else {                         // B: 256 rows x 128B
                int i2  = idx - 512;
                int r   = i2 >> 3;
                int seg = i2 & 7;
                cp_async16(base + 8192 + SWZ((uint32_t)(r * 128 + seg * 16)),
                           Wo + ((size_t)r * 256 + p * 64 + seg * 8));
            }
        }
    };

    auto compute = [&](int buf) {
        const uint32_t base  = sb + buf * 40960;
        const uint32_t bbase = base + 8192;
        const int j = lane >> 3, r = lane & 7;
        #pragma unroll
        for (int c = 0; c < 2; c++) {
            #pragma unroll
            for (int g = 0; g < 2; g++) {
                uint32_t bfr[2][4];
                #pragma unroll
                for (int nt = 0; nt < 2; nt++) {
                    uint32_t row  = wn + nt * 16 + (j >> 1) * 8 + r;
                    uint32_t colb = (c * 32 + g * 16 + (j & 1) * 8) * 2;
                    ldsm4(bfr[nt], bbase + SWZ(row * 128 + colb));
                }
                #pragma unroll
                for (int t = 0; t < 2; t++) {
                    #pragma unroll
                    for (int mt = 0; mt < 2; mt++) {
                        uint32_t af[4];
                        uint32_t row  = mt * 16 + (j & 1) * 8 + r;
                        uint32_t colb = (t * 32 + g * 16 + (j >> 1) * 8) * 2;
                        ldsm4(af, base + c * 4096 + SWZ(row * 128 + colb));
                        #pragma unroll
                        for (int ns = 0; ns < 4; ns++)
                            mma_f16(acc[mt][ns], af,
                                    bfr[ns >> 1][(ns & 1) * 2],
                                    bfr[ns >> 1][(ns & 1) * 2 + 1]);
                    }
                }
            }
        }
    };

    prefetch(0, 0);
    CP_ASYNC_COMMIT();
    #pragma unroll 1
    for (int p = 0; p < 4; p++) {
        int buf = p & 1;
        if (p + 1 < 4) {
            prefetch(p + 1, buf ^ 1);
            CP_ASYNC_COMMIT();
            CP_ASYNC_WAIT(1);
        } else {
            CP_ASYNC_WAIT(0);
        }
        __syncthreads();
        compute(buf);
        __syncthreads();
    }

    const int g = lane >> 2, tig = lane & 3;
    #pragma unroll
    for (int mt = 0; mt < 2; mt++) {
        int mr = m0 + mt * 16 + g;
        #pragma unroll
        for (int ns = 0; ns < 4; ns++) {
            int col = wn + ns * 8 + tig * 2;
            float bxv = b_out[col], byv = b_out[col + 1];
            if (mr < Mq) {
                float2 o = {acc[mt][ns][0] + bxv, acc[mt][ns][1] + byv};
                *(float2*)&C[(size_t)mr * 256 + col] = o;
            }
            if (mr + 8 < Mq) {
                float2 o = {acc[mt][ns][2] + bxv, acc[mt][ns][3] + byv};
                *(float2*)&C[(size_t)(mr + 8) * 256 + col] = o;
            }
        }
    }
}

// ---------------------------------------------------------------------------
// Deformable sampling v3: TWO queries per block, half2 gathers.
// Phase 1: 256 threads = 2 queries x 128 (h,l,p) combos -> idx/weights.
// Phase 2: thread = (q, h, d2); each thread covers 2 dims via __half2 loads.
// ---------------------------------------------------------------------------
__global__ __launch_bounds__(256)
void msda_sample2(const __half* __restrict__ vproj,
                  const float* __restrict__ refp,
                  const float* __restrict__ off,
                  const float* __restrict__ logits,
                  const int*   __restrict__ shapes,
                  const int*   __restrict__ lstart,
                  __half* __restrict__ sampf,     // [3712, 512] chunked hi|lo
                  int Lq, int Lv)
{
    const int bq0 = blockIdx.x * 2;
    const int tid = threadIdx.x;
    const int q   = tid >> 7;            // 0/1: query within pair
    const int c   = tid & 127;           // combo / lane-within-query

    __shared__ float s_log[2][128];
    __shared__ float s_off[2][256];
    __shared__ float s_ref[2][8];
    __shared__ int   s_shape[8];
    __shared__ int   s_start[4];
    __shared__ int4   s_idx4[2][128];
    __shared__ float4 s_w4[2][128];

    s_log[q][c]       = logits[(size_t)(bq0 + q) * 128 + c];
    s_off[q][c]       = off[(size_t)(bq0 + q) * 256 + c];
    s_off[q][c + 128] = off[(size_t)(bq0 + q) * 256 + c + 128];
    if (tid < 16) s_ref[tid >> 3][tid & 7] =
        refp[(size_t)(bq0 + (tid >> 3)) * 8 + (tid & 7)];
    if (tid < 8) s_shape[tid] = shapes[tid];
    if (tid < 4) s_start[tid] = lstart[tid];
    __syncthreads();

    // ---- phase 1: one combo per thread ----
    {
        const int h = c >> 4;
        const int l = (c >> 2) & 3;

        float mx = -1e30f;
        #pragma unroll
        for (int j = 0; j < 16; j++) mx = fmaxf(mx, s_log[q][h * 16 + j]);
        float sum = 0.f;
        #pragma unroll
        for (int j = 0; j < 16; j++) sum += __expf(s_log[q][h * 16 + j] - mx);
        const float aw = __expf(s_log[q][c] - mx) / sum;

        const int   Hh = s_shape[l * 2 + 0];
        const int   Ww = s_shape[l * 2 + 1];
        const float Wfl = (float)Ww, Hfl = (float)Hh;
        const int   st = s_start[l];
        const float rx = s_ref[q][l * 2 + 0];
        const float ry = s_ref[q][l * 2 + 1];

        const float x = (rx + s_off[q][c * 2 + 0] / Wfl) * Wfl - 0.5f;
        const float y = (ry + s_off[q][c * 2 + 1] / Hfl) * Hfl - 0.5f;
        const float x0f = floorf(x), y0f = floorf(y);
        const float lx = x - x0f, ly = y - y0f;
        const int   x0 = (int)x0f, y0 = (int)y0f;

        const bool vx0 = (x0 >= 0) & (x0 < Ww);
        const bool vx1 = (x0 + 1 >= 0) & (x0 + 1 < Ww);
        const bool vy0 = (y0 >= 0) & (y0 < Hh);
        const bool vy1 = (y0 + 1 >= 0) & (y0 + 1 < Hh);

        int4 id;
        id.x = (vy0 && vx0) ? st + y0 * Ww + x0           : -1;
        id.y = (vy0 && vx1) ? st + y0 * Ww + x0 + 1       : -1;
        id.z = (vy1 && vx0) ? st + (y0 + 1) * Ww + x0     : -1;
        id.w = (vy1 && vx1) ? st + (y0 + 1) * Ww + x0 + 1 : -1;

        float4 ww;
        ww.x = aw * (1.f - lx) * (1.f - ly);
        ww.y = aw * lx * (1.f - ly);
        ww.z = aw * (1.f - lx) * ly;
        ww.w = aw * lx * ly;

        s_idx4[q][c] = id;
        s_w4[q][c]   = ww;
    }
    __syncthreads();

    // ---- phase 2: thread (q, h, d2); 2 dims via half2 ----
    const int h  = c >> 4;
    const int d2 = c & 15;
    const int bq = bq0 + q;
    const int b  = bq / Lq;
    const __half2* vb = (const __half2*)(vproj + (size_t)b * Lv * EMBED
                                         + h * HEAD_DIM + d2 * 2);

    float2 a0 = {0.f, 0.f}, a1 = {0.f, 0.f}, a2 = {0.f, 0.f}, a3 = {0.f, 0.f};
    #pragma unroll 4
    for (int i = 0; i < 16; i++) {
        const int t = h * 16 + i;
        const int4   id = s_idx4[q][t];
        const float4 ww = s_w4[q][t];
        if (id.x >= 0) {
            float2 f = __half22float2(__ldg(vb + (size_t)id.x * 128));
            a0.x += ww.x * f.x; a0.y += ww.x * f.y;
        }
        if (id.y >= 0) {
            float2 f = __half22float2(__ldg(vb + (size_t)id.y * 128));
            a1.x += ww.y * f.x; a1.y += ww.y * f.y;
        }
        if (id.z >= 0) {
            float2 f = __half22float2(__ldg(vb + (size_t)id.z * 128));
            a2.x += ww.z * f.x; a2.y += ww.z * f.y;
        }
        if (id.w >= 0) {
            float2 f = __half22float2(__ldg(vb + (size_t)id.w * 128));
            a3.x += ww.w * f.x; a3.y += ww.w * f.y;
        }
    }
    const float rx2 = (a0.x + a1.x) + (a2.x + a3.x);
    const float ry2 = (a0.y + a1.y) + (a2.y + a3.y);

    // write hi|lo split, two contiguous dims -> half2 stores
    __half hx = __float2half_rn(rx2);
    __half hy = __float2half_rn(ry2);
    __half lx2 = __float2half_rn(rx2 - __half2float(hx));
    __half ly2 = __float2half_rn(ry2 - __half2float(hy));
    __half2* dst = (__half2*)(sampf + (size_t)bq * 512 + h * 64 + d2 * 2);
    dst[0]  = __halves2half2(hx, hy);
    dst[16] = __halves2half2(lx2, ly2);   // +32 halves
}

// ---------------------------------------------------------------------------
// kernel_launch
// ---------------------------------------------------------------------------
extern "C" void kernel_launch(void* const* d_in, const int* in_sizes, int n_in,
                              void* d_out, int out_size)
{
    const float* query   = (const float*)d_in[0];
    const float* refp    = (const float*)d_in[1];
    const float* value   = (const float*)d_in[2];
    const int*   shapes  = (const int*)  d_in[3];
    const int*   lstart  = (const int*)  d_in[4];
    const float* w_value = (const float*)d_in[5];
    const float* b_value = (const float*)d_in[6];
    const float* w_off   = (const float*)d_in[7];
    const float* b_off   = (const float*)d_in[8];
    const float* w_attn  = (const float*)d_in[9];
    const float* b_attn  = (const float*)d_in[10];
    const float* w_out   = (const float*)d_in[11];
    const float* b_out   = (const float*)d_in[12];

    const int Mv = in_sizes[2] / EMBED;   // bs * Lv = 53176
    const int Mq = in_sizes[0] / EMBED;   // bs * Lq = 3600
    const int bs = 4;
    const int Lv = Mv / bs;
    const int Lq = Mq / bs;

    float *offb, *logitb;
    __half *af, *vph, *wf, *sf;
    cudaGetSymbolAddress((void**)&offb,   g_off);
    cudaGetSymbolAddress((void**)&logitb, g_logit);
    cudaGetSymbolAddress((void**)&af,     g_af16);
    cudaGetSymbolAddress((void**)&vph,    g_vph);
    cudaGetSymbolAddress((void**)&wf,     g_wf16);
    cudaGetSymbolAddress((void**)&sf,     g_sampf16);

    // 1) convert value + weights to fp16
    {
        int total = (Mv + 512) * 32;
        cvt_f16<<<(total + 255) / 256, 256>>>(value, w_value, w_out, af, wf, Mv);
    }

    // 2) fat kernel: small GEMMs first, then vproj (fp16 tensor) -> fp16 out
    const int MB = (Mv + 127) / 128;               // 416
    static bool cfg = false;
    if (!cfg) {
        cudaFuncSetAttribute(fat_gemms,
                             cudaFuncAttributeMaxDynamicSharedMemorySize, 65536);
        cudaFuncSetAttribute(outproj_mma32,
                             cudaFuncAttributeMaxDynamicSharedMemorySize, 81920);
        cfg = true;
    }
    fat_gemms<<<342 + 2 * MB, 256, 65536>>>(
        af, wf, b_value, vph, Mv, MB,
        query, w_off, b_off, offb, w_attn, b_attn, logitb, Mq);

    // 3) sampling: 2 queries per block, half2 gathers -> fp16 split
    msda_sample2<<<Mq / 2, 256>>>(vph, refp, offb, logitb, shapes, lstart,
                                  sf, Lq, Lv);

    // 4) output projection (fp16, 2-term samp split, 32-row tiles) -> d_out
    outproj_mma32<<<(Mq + 31) / 32, 256, 81920>>>(sf, wf, b_out, (float*)d_out, Mq);
}

// round 16
// speedup vs baseline: 1.8599x; 1.2678x over previous
#include <cuda_runtime.h>
#include <cuda_fp16.h>
#include <cstdint>
#include <cstddef>

#define EMBED    256
#define HEADS    8
#define LEVELS   4
#define POINTS   4
#define HEAD_DIM 32

// ---------------------------------------------------------------------------
// Scratch (static __device__ globals; runtime allocation is forbidden)
// ---------------------------------------------------------------------------
__device__ __half g_af16[53248 * 256];   // value (fp16 input to vproj)
__device__ __half g_vph [53248 * 256];   // projected value (fp16)
__device__ __half g_wf16[896 * 256];     // wv 0-255 | wo 256-511 | woff 512-767 | wattn 768-895
__device__ __half g_qf16[3712 * 256];    // query fp16
__device__ float  g_qout[3600 * 384];    // offsets (0-255) | logits (256-383)
__device__ __half g_sampf16[3712 * 256]; // sampled out (plain fp16)

// ---------------------------------------------------------------------------
// helpers
// ---------------------------------------------------------------------------
__device__ __forceinline__ uint32_t smem_u32(const void* p) {
    uint32_t a;
    asm("{ .reg .u64 t; cvta.to.shared.u64 t, %1; cvt.u32.u64 %0, t; }"
        : "=r"(a) : "l"(p));
    return a;
}

__device__ __forceinline__ void ldsm4(uint32_t* r, uint32_t addr) {
    asm volatile("ldmatrix.sync.aligned.m8n8.x4.shared.b16 {%0,%1,%2,%3}, [%4];"
                 : "=r"(r[0]), "=r"(r[1]), "=r"(r[2]), "=r"(r[3]) : "r"(addr));
}

__device__ __forceinline__ void mma_f16(float* c, const uint32_t* a,
                                        uint32_t b0, uint32_t b1) {
    asm volatile(
        "mma.sync.aligned.m16n8k16.row.col.f32.f16.f16.f32 "
        "{%0,%1,%2,%3}, {%4,%5,%6,%7}, {%8,%9}, {%0,%1,%2,%3};"
        : "+f"(c[0]), "+f"(c[1]), "+f"(c[2]), "+f"(c[3])
        : "r"(a[0]), "r"(a[1]), "r"(a[2]), "r"(a[3]), "r"(b0), "r"(b1));
}

__device__ __forceinline__ void cp_async16(uint32_t saddr, const void* gaddr) {
    asm volatile("cp.async.cg.shared.global [%0], [%1], 16;"
                 :: "r"(saddr), "l"(gaddr) : "memory");
}
#define CP_ASYNC_COMMIT() asm volatile("cp.async.commit_group;" ::: "memory")
#define CP_ASYNC_WAIT(N)  asm volatile("cp.async.wait_group %0;" :: "n"(N) : "memory")

union Pack8h { uint4 u; __half b[8]; __half2 h2[4]; };

#define SWZ(o) ((o) ^ (((o) >> 3) & 0x70))

// ---------------------------------------------------------------------------
// Convert to fp16: value rows [0,Mv) -> Af; weights (wv,wo,woff,wattn = 896
// rows) -> Wf; query rows -> Qf.
// ---------------------------------------------------------------------------
__global__ __launch_bounds__(256)
void cvt_f16(const float* __restrict__ A,
             const float* __restrict__ Wv, const float* __restrict__ Wo,
             const float* __restrict__ Woff, const float* __restrict__ Wattn,
             const float* __restrict__ Q,
             __half* __restrict__ Af, __half* __restrict__ Wf,
             __half* __restrict__ Qf, int Mv, int Mq)
{
    int t = blockIdx.x * 256 + threadIdx.x;      // one thread per 8 floats
    int total = (Mv + 896 + Mq) * 32;
    if (t >= total) return;
    int row = t >> 5;
    int s8  = t & 31;
    const float* src;
    __half* dst;
    if (row < Mv) {
        src = A + (size_t)row * 256 + s8 * 8;
        dst = Af + (size_t)row * 256 + s8 * 8;
    } else if (row < Mv + 896) {
        int r2 = row - Mv;
        if      (r2 < 256) src = Wv   + (size_t)r2 * 256 + s8 * 8;
        else if (r2 < 512) src = Wo   + (size_t)(r2 - 256) * 256 + s8 * 8;
        else if (r2 < 768) src = Woff + (size_t)(r2 - 512) * 256 + s8 * 8;
        else               src = Wattn+ (size_t)(r2 - 768) * 256 + s8 * 8;
        dst = Wf + (size_t)r2 * 256 + s8 * 8;
    } else {
        int r3 = row - Mv - 896;
        src = Q  + (size_t)r3 * 256 + s8 * 8;
        dst = Qf + (size_t)r3 * 256 + s8 * 8;
    }
    float4 v0 = *(const float4*)(src);
    float4 v1 = *(const float4*)(src + 4);
    Pack8h H;
    H.h2[0] = __floats2half2_rn(v0.x, v0.y);
    H.h2[1] = __floats2half2_rn(v0.z, v0.w);
    H.h2[2] = __floats2half2_rn(v1.x, v1.y);
    H.h2[3] = __floats2half2_rn(v1.z, v1.w);
    *(uint4*)dst = H.u;
}

// ---------------------------------------------------------------------------
// fp16 MMA GEMM body, 128x128 tile. Template over output: OUT_HALF writes
// fp16 with ldc=256; otherwise fp32 with arbitrary ldc (bias0 indexed locally).
// ---------------------------------------------------------------------------
template <bool OUT_HALF>
__device__ __forceinline__ void mma_gemm_128(
    const __half* __restrict__ Af, const __half* __restrict__ Bf,
    const float* __restrict__ bias0,     // bias for this 128-col tile
    void* __restrict__ Cp, int ldc, int M, int m0, int n0, char* sm)
{
    const int tid  = threadIdx.x;
    const int lane = tid & 31;
    const int w    = tid >> 5;
    const int wm   = (w & 1) * 64;
    const int wn   = (w >> 1) * 32;
    const uint32_t sb = smem_u32(sm);

    float acc[4][4][4] = {};

    auto prefetch = [&](int p, int buf) {
        const uint32_t base = sb + buf * 32768;
        #pragma unroll
        for (int i = 0; i < 8; i++) {
            int idx = tid + i * 256;             // 0..2047
            int r   = (idx >> 3) & 127;
            int seg = idx & 7;
            uint32_t so = SWZ((uint32_t)(r * 128 + seg * 16));
            if (idx < 1024) {
                cp_async16(base + so,
                           Af + ((size_t)(m0 + r) * 256 + p * 64 + seg * 8));
            } else {
                cp_async16(base + 16384 + so,
                           Bf + ((size_t)(n0 + r) * 256 + p * 64 + seg * 8));
            }
        }
    };

    auto compute = [&](int buf) {
        const uint32_t abase = sb + buf * 32768;
        const uint32_t bbase = abase + 16384;
        const int j = lane >> 3, r = lane & 7;
        #pragma unroll
        for (int g = 0; g < 4; g++) {
            uint32_t bfr[2][4];
            #pragma unroll
            for (int nt = 0; nt < 2; nt++) {
                uint32_t row  = wn + nt * 16 + (j >> 1) * 8 + r;
                uint32_t colb = (g * 16 + (j & 1) * 8) * 2;
                ldsm4(bfr[nt], bbase + SWZ(row * 128 + colb));
            }
            #pragma unroll
            for (int mt = 0; mt < 4; mt++) {
                uint32_t af[4];
                uint32_t row  = wm + mt * 16 + (j & 1) * 8 + r;
                uint32_t colb = (g * 16 + (j >> 1) * 8) * 2;
                ldsm4(af, abase + SWZ(row * 128 + colb));
                #pragma unroll
                for (int ns = 0; ns < 4; ns++)
                    mma_f16(acc[mt][ns], af,
                            bfr[ns >> 1][(ns & 1) * 2],
                            bfr[ns >> 1][(ns & 1) * 2 + 1]);
            }
        }
    };

    prefetch(0, 0);
    CP_ASYNC_COMMIT();
    #pragma unroll 1
    for (int p = 0; p < 4; p++) {
        int buf = p & 1;
        if (p + 1 < 4) {
            prefetch(p + 1, buf ^ 1);
            CP_ASYNC_COMMIT();
            CP_ASYNC_WAIT(1);
        } else {
            CP_ASYNC_WAIT(0);
        }
        __syncthreads();
        compute(buf);
        __syncthreads();
    }

    const int g = lane >> 2, tig = lane & 3;
    #pragma unroll
    for (int mt = 0; mt < 4; mt++) {
        int mr = m0 + wm + mt * 16 + g;
        #pragma unroll
        for (int ns = 0; ns < 4; ns++) {
            int lc = wn + ns * 8 + tig * 2;      // local col in 128-tile
            float bxv = bias0[lc], byv = bias0[lc + 1];
            if (OUT_HALF) {
                __half* C = (__half*)Cp;
                if (mr < M) {
                    __half2 o = __floats2half2_rn(acc[mt][ns][0] + bxv,
                                                  acc[mt][ns][1] + byv);
                    *(__half2*)&C[(size_t)mr * 256 + n0 + lc] = o;
                }
                if (mr + 8 < M) {
                    __half2 o = __floats2half2_rn(acc[mt][ns][2] + bxv,
                                                  acc[mt][ns][3] + byv);
                    *(__half2*)&C[(size_t)(mr + 8) * 256 + n0 + lc] = o;
                }
            } else {
                float* C = (float*)Cp;
                if (mr < M) {
                    float2 o = {acc[mt][ns][0] + bxv, acc[mt][ns][1] + byv};
                    *(float2*)&C[(size_t)mr * ldc + n0 + lc] = o;
                }
                if (mr + 8 < M) {
                    float2 o = {acc[mt][ns][2] + bxv, acc[mt][ns][3] + byv};
                    *(float2*)&C[(size_t)(mr + 8) * ldc + n0 + lc] = o;
                }
            }
        }
    }
}

// ---------------------------------------------------------------------------
// Fat kernel (2 CTAs/SM):
//   blocks [0,87)        : combined query GEMM [Mq,384] fp32 out (87 = 29x3)
//   blocks [87, 87+2MB)  : vproj fp16 mma -> fp16 out
// ---------------------------------------------------------------------------
__global__ __launch_bounds__(256, 2)
void fat_gemms(const __half* __restrict__ Af, const __half* __restrict__ Wf,
               const float* __restrict__ b_value,
               __half* __restrict__ Cv, int Mv,
               const __half* __restrict__ Qf,
               const float* __restrict__ b_off, const float* __restrict__ b_attn,
               float* __restrict__ qout, int Mq)
{
    extern __shared__ char sm[];
    const int bx = blockIdx.x;

    if (bx < 87) {
        int mt = bx / 3, nt = bx % 3;
        int n0 = nt * 128;
        const float* bias0 = (n0 < 256) ? b_off + n0 : b_attn;
        mma_gemm_128<false>(Qf, Wf + 512 * 256, bias0, qout, 384, Mq,
                            mt * 128, n0, sm);
        return;
    }
    int vb = bx - 87;
    mma_gemm_128<true>(Af, Wf, b_value + (vb & 1) * 128, Cv, 256, Mv,
                       (vb >> 1) * 128, (vb & 1) * 128, sm);
}

// ---------------------------------------------------------------------------
// Output projection: tile 32x256, single-term fp16 samp, w_out rows 256-511.
// smem/stage: A 4KB + B 32KB = 36KB; double buffered = 72KB.
// ---------------------------------------------------------------------------
__global__ __launch_bounds__(256)
void outproj_mma32(const __half* __restrict__ Sf, const __half* __restrict__ Wf,
                   const float* __restrict__ b_out, float* __restrict__ C, int Mq)
{
    extern __shared__ char sm[];
    const int tid  = threadIdx.x;
    const int lane = tid & 31;
    const int w    = tid >> 5;
    const int wn   = w * 32;                 // each warp owns 32 output cols
    const int m0   = blockIdx.x * 32;
    const uint32_t sb = smem_u32(sm);
    const __half* Wo = Wf + 256 * 256;

    float acc[2][4][4] = {};

    auto prefetch = [&](int p, int buf) {
        const uint32_t base = sb + buf * 36864;
        #pragma unroll
        for (int i = 0; i < 9; i++) {
            int idx = tid + i * 256;         // 0..2303
            if (idx < 256) {                 // A: 32 rows x 128B
                int r   = idx >> 3;
                int seg = idx & 7;
                cp_async16(base + SWZ((uint32_t)(r * 128 + seg * 16)),
                           Sf + ((size_t)(m0 + r) * 256 + p * 64 + seg * 8));
            } else {                         // B: 256 rows x 128B
                int i2  = idx - 256;
                int r   = i2 >> 3;
                int seg = i2 & 7;
                cp_async16(base + 4096 + SWZ((uint32_t)(r * 128 + seg * 16)),
                           Wo + ((size_t)r * 256 + p * 64 + seg * 8));
            }
        }
    };

    auto compute = [&](int buf) {
        const uint32_t abase = sb + buf * 36864;
        const uint32_t bbase = abase + 4096;
        const int j = lane >> 3, r = lane & 7;
        #pragma unroll
        for (int g = 0; g < 4; g++) {
            uint32_t bfr[2][4];
            #pragma unroll
            for (int nt = 0; nt < 2; nt++) {
                uint32_t row  = wn + nt * 16 + (j >> 1) * 8 + r;
                uint32_t colb = (g * 16 + (j & 1) * 8) * 2;
                ldsm4(bfr[nt], bbase + SWZ(row * 128 + colb));
            }
            #pragma unroll
            for (int mt = 0; mt < 2; mt++) {
                uint32_t af[4];
                uint32_t row  = mt * 16 + (j & 1) * 8 + r;
                uint32_t colb = (g * 16 + (j >> 1) * 8) * 2;
                ldsm4(af, abase + SWZ(row * 128 + colb));
                #pragma unroll
                for (int ns = 0; ns < 4; ns++)
                    mma_f16(acc[mt][ns], af,
                            bfr[ns >> 1][(ns & 1) * 2],
                            bfr[ns >> 1][(ns & 1) * 2 + 1]);
            }
        }
    };

    prefetch(0, 0);
    CP_ASYNC_COMMIT();
    #pragma unroll 1
    for (int p = 0; p < 4; p++) {
        int buf = p & 1;
        if (p + 1 < 4) {
            prefetch(p + 1, buf ^ 1);
            CP_ASYNC_COMMIT();
            CP_ASYNC_WAIT(1);
        } else {
            CP_ASYNC_WAIT(0);
        }
        __syncthreads();
        compute(buf);
        __syncthreads();
    }

    const int g = lane >> 2, tig = lane & 3;
    #pragma unroll
    for (int mt = 0; mt < 2; mt++) {
        int mr = m0 + mt * 16 + g;
        #pragma unroll
        for (int ns = 0; ns < 4; ns++) {
            int col = wn + ns * 8 + tig * 2;
            float bxv = b_out[col], byv = b_out[col + 1];
            if (mr < Mq) {
                float2 o = {acc[mt][ns][0] + bxv, acc[mt][ns][1] + byv};
                *(float2*)&C[(size_t)mr * 256 + col] = o;
            }
            if (mr + 8 < Mq) {
                float2 o = {acc[mt][ns][2] + bxv, acc[mt][ns][3] + byv};
                *(float2*)&C[(size_t)(mr + 8) * 256 + col] = o;
            }
        }
    }
}

// ---------------------------------------------------------------------------
// Deformable sampling: 2 queries per block, half2 gathers, plain fp16 output.
// offsets/logits read from combined qout [row, 384].
// ---------------------------------------------------------------------------
__global__ __launch_bounds__(256)
void msda_sample2(const __half* __restrict__ vproj,
                  const float* __restrict__ refp,
                  const float* __restrict__ qout,
                  const int*   __restrict__ shapes,
                  const int*   __restrict__ lstart,
                  __half* __restrict__ sampf,     // [3712, 256] plain fp16
                  int Lq, int Lv)
{
    const int bq0 = blockIdx.x * 2;
    const int tid = threadIdx.x;
    const int q   = tid >> 7;            // 0/1: query within pair
    const int c   = tid & 127;           // combo / lane-within-query

    __shared__ float s_log[2][128];
    __shared__ float s_off[2][256];
    __shared__ float s_ref[2][8];
    __shared__ int   s_shape[8];
    __shared__ int   s_start[4];
    __shared__ int4   s_idx4[2][128];
    __shared__ float4 s_w4[2][128];

    const float* qrow = qout + (size_t)(bq0 + q) * 384;
    s_log[q][c]       = qrow[256 + c];
    s_off[q][c]       = qrow[c];
    s_off[q][c + 128] = qrow[c + 128];
    if (tid < 16) s_ref[tid >> 3][tid & 7] =
        refp[(size_t)(bq0 + (tid >> 3)) * 8 + (tid & 7)];
    if (tid < 8) s_shape[tid] = shapes[tid];
    if (tid < 4) s_start[tid] = lstart[tid];
    __syncthreads();

    // ---- phase 1: one combo per thread ----
    {
        const int h = c >> 4;
        const int l = (c >> 2) & 3;

        float mx = -1e30f;
        #pragma unroll
        for (int j = 0; j < 16; j++) mx = fmaxf(mx, s_log[q][h * 16 + j]);
        float sum = 0.f;
        #pragma unroll
        for (int j = 0; j < 16; j++) sum += __expf(s_log[q][h * 16 + j] - mx);
        const float aw = __expf(s_log[q][c] - mx) / sum;

        const int   Hh = s_shape[l * 2 + 0];
        const int   Ww = s_shape[l * 2 + 1];
        const float Wfl = (float)Ww, Hfl = (float)Hh;
        const int   st = s_start[l];
        const float rx = s_ref[q][l * 2 + 0];
        const float ry = s_ref[q][l * 2 + 1];

        const float x = (rx + s_off[q][c * 2 + 0] / Wfl) * Wfl - 0.5f;
        const float y = (ry + s_off[q][c * 2 + 1] / Hfl) * Hfl - 0.5f;
        const float x0f = floorf(x), y0f = floorf(y);
        const float lx = x - x0f, ly = y - y0f;
        const int   x0 = (int)x0f, y0 = (int)y0f;

        const bool vx0 = (x0 >= 0) & (x0 < Ww);
        const bool vx1 = (x0 + 1 >= 0) & (x0 + 1 < Ww);
        const bool vy0 = (y0 >= 0) & (y0 < Hh);
        const bool vy1 = (y0 + 1 >= 0) & (y0 + 1 < Hh);

        int4 id;
        id.x = (vy0 && vx0) ? st + y0 * Ww + x0           : -1;
        id.y = (vy0 && vx1) ? st + y0 * Ww + x0 + 1       : -1;
        id.z = (vy1 && vx0) ? st + (y0 + 1) * Ww + x0     : -1;
        id.w = (vy1 && vx1) ? st + (y0 + 1) * Ww + x0 + 1 : -1;

        float4 ww;
        ww.x = aw * (1.f - lx) * (1.f - ly);
        ww.y = aw * lx * (1.f - ly);
        ww.z = aw * (1.f - lx) * ly;
        ww.w = aw * lx * ly;

        s_idx4[q][c] = id;
        s_w4[q][c]   = ww;
    }
    __syncthreads();

    // ---- phase 2: thread (q, h, d2); 2 dims via half2 ----
    const int h  = c >> 4;
    const int d2 = c & 15;
    const int bq = bq0 + q;
    const int b  = bq / Lq;
    const __half2* vb = (const __half2*)(vproj + (size_t)b * Lv * EMBED
                                         + h * HEAD_DIM + d2 * 2);

    float2 a0 = {0.f, 0.f}, a1 = {0.f, 0.f}, a2 = {0.f, 0.f}, a3 = {0.f, 0.f};
    #pragma unroll 4
    for (int i = 0; i < 16; i++) {
        const int t = h * 16 + i;
        const int4   id = s_idx4[q][t];
        const float4 ww = s_w4[q][t];
        if (id.x >= 0) {
            float2 f = __half22float2(__ldg(vb + (size_t)id.x * 128));
            a0.x += ww.x * f.x; a0.y += ww.x * f.y;
        }
        if (id.y >= 0) {
            float2 f = __half22float2(__ldg(vb + (size_t)id.y * 128));
            a1.x += ww.y * f.x; a1.y += ww.y * f.y;
        }
        if (id.z >= 0) {
            float2 f = __half22float2(__ldg(vb + (size_t)id.z * 128));
            a2.x += ww.z * f.x; a2.y += ww.z * f.y;
        }
        if (id.w >= 0) {
            float2 f = __half22float2(__ldg(vb + (size_t)id.w * 128));
            a3.x += ww.w * f.x; a3.y += ww.w * f.y;
        }
    }
    const float rx2 = (a0.x + a1.x) + (a2.x + a3.x);
    const float ry2 = (a0.y + a1.y) + (a2.y + a3.y);

    __half2* dst = (__half2*)(sampf + (size_t)bq * 256 + h * HEAD_DIM + d2 * 2);
    *dst = __floats2half2_rn(rx2, ry2);
}

// ---------------------------------------------------------------------------
// kernel_launch
// ---------------------------------------------------------------------------
extern "C" void kernel_launch(void* const* d_in, const int* in_sizes, int n_in,
                              void* d_out, int out_size)
{
    const float* query   = (const float*)d_in[0];
    const float* refp    = (const float*)d_in[1];
    const float* value   = (const float*)d_in[2];
    const int*   shapes  = (const int*)  d_in[3];
    const int*   lstart  = (const int*)  d_in[4];
    const float* w_value = (const float*)d_in[5];
    const float* b_value = (const float*)d_in[6];
    const float* w_off   = (const float*)d_in[7];
    const float* b_off   = (const float*)d_in[8];
    const float* w_attn  = (const float*)d_in[9];
    const float* b_attn  = (const float*)d_in[10];
    const float* w_out   = (const float*)d_in[11];
    const float* b_out   = (const float*)d_in[12];

    const int Mv = in_sizes[2] / EMBED;   // bs * Lv = 53176
    const int Mq = in_sizes[0] / EMBED;   // bs * Lq = 3600
    const int bs = 4;
    const int Lv = Mv / bs;
    const int Lq = Mq / bs;

    float *qoutb;
    __half *af, *vph, *wf, *qf, *sf;
    cudaGetSymbolAddress((void**)&af,     g_af16);
    cudaGetSymbolAddress((void**)&vph,    g_vph);
    cudaGetSymbolAddress((void**)&wf,     g_wf16);
    cudaGetSymbolAddress((void**)&qf,     g_qf16);
    cudaGetSymbolAddress((void**)&qoutb,  g_qout);
    cudaGetSymbolAddress((void**)&sf,     g_sampf16);

    // 1) convert value + all weights + query to fp16
    {
        int total = (Mv + 896 + Mq) * 32;
        cvt_f16<<<(total + 255) / 256, 256>>>(value, w_value, w_out, w_off,
                                              w_attn, query, af, wf, qf, Mv, Mq);
    }

    // 2) fat kernel: combined query GEMM (87 MMA blocks) + vproj (832 blocks)
    const int MB = (Mv + 127) / 128;               // 416
    static bool cfg = false;
    if (!cfg) {
        cudaFuncSetAttribute(fat_gemms,
                             cudaFuncAttributeMaxDynamicSharedMemorySize, 65536);
        cudaFuncSetAttribute(outproj_mma32,
                             cudaFuncAttributeMaxDynamicSharedMemorySize, 73728);
        cfg = true;
    }
    fat_gemms<<<87 + 2 * MB, 256, 65536>>>(
        af, wf, b_value, vph, Mv, qf, b_off, b_attn, qoutb, Mq);

    // 3) sampling: 2 queries per block, half2 gathers -> plain fp16
    msda_sample2<<<Mq / 2, 256>>>(vph, refp, qoutb, shapes, lstart,
                                  sf, Lq, Lv);

    // 4) output projection (single-term fp16) -> d_out
    outproj_mma32<<<(Mq + 31) / 32, 256, 73728>>>(sf, wf, b_out,
                                                  (float*)d_out, Mq);
}